// round 2
// baseline (speedup 1.0000x reference)
#include <cuda_runtime.h>
#include <cuda_bf16.h>
#include <cstdint>

// CapsuleRouting: b=8, B=144, C=16, P2=16, f*f=144, ITERS=3
// Key facts:
//  - input `a` cancels in softmax (constant over C) -> ignored
//  - 3 streaming passes over u (one per iteration), r-update fused with
//    next softmax + weighted-sum in a single pass over B-chunks
//  - a_out = sn/(1+sn) where sn = |s|^2

#define B_N   144
#define C_N   16
#define P_N   16
#define F2_N  144
#define XT    8            // x positions per block
#define NTILE 18           // 144 / XT
#define BCH   2            // B per chunk
#define NCHUNK 72          // 144 / BCH
#define PLANE 132          // P_N*XT + 4 padding (bank-conflict-free)

// smem layout (floats)
#define U_S_OFF    0
#define U_S_SIZE   (2 * BCH * C_N * PLANE)        // 8448  (double buffered)
#define R_S_OFF    (U_S_OFF + U_S_SIZE)           // r[B][C][XT]
#define R_S_SIZE   (B_N * C_N * XT)               // 18432
#define V_S_OFF    (R_S_OFF + R_S_SIZE)
#define V_S_SIZE   (C_N * PLANE)                  // 2112
#define C_S_OFF    (V_S_OFF + V_S_SIZE)
#define C_S_SIZE   (BCH * C_N * XT)               // 256
#define P_S_OFF    (C_S_OFF + C_S_SIZE)
#define P_S_SIZE   (2 * C_N * XT)                 // 256
#define SMEM_FLOATS (P_S_OFF + P_S_SIZE)          // 29504
#define SMEM_BYTES  (SMEM_FLOATS * 4)             // 118016

#define V_ELEMS (8 * C_N * P_N * F2_N)            // 294912

__device__ __forceinline__ void cp_async16(float* smem_dst, const float* gmem_src) {
    unsigned s = (unsigned)__cvta_generic_to_shared(smem_dst);
    asm volatile("cp.async.cg.shared.global [%0], [%1], 16;\n" :: "r"(s), "l"(gmem_src));
}
__device__ __forceinline__ void cp_commit() {
    asm volatile("cp.async.commit_group;\n");
}

// prefetch one B-chunk (BCH*C_N*P_N*XT = 4096 floats) into smem buffer
__device__ __forceinline__ void prefetch_chunk(const float* __restrict__ ub,
                                               float* __restrict__ u_s,
                                               int ch, int buf, int x0, int t) {
    float* dst = u_s + buf * (BCH * C_N * PLANE);
    int B0 = ch * BCH;
#pragma unroll
    for (int k = 0; k < 4; k++) {
        int q    = t + k * 256;        // 0..1023 float4 slots
        int row  = q >> 1;             // 0..511 : (B', C, p)
        int half = q & 1;
        int Bl = row >> 8;
        int Cl = (row >> 4) & 15;
        int pl = row & 15;
        const float* g = ub + ((size_t)((B0 + Bl) * C_N + Cl) * P_N + pl) * F2_N
                            + x0 + half * 4;
        float* s = dst + (Bl * C_N + Cl) * PLANE + pl * XT + half * 4;
        cp_async16(s, g);
    }
    cp_commit();
}

__global__ void __launch_bounds__(256, 1)
caps_route_kernel(const float* __restrict__ u, float* __restrict__ out) {
    extern __shared__ float sm[];
    float* u_s  = sm + U_S_OFF;
    float* r_s  = sm + R_S_OFF;
    float* v_s  = sm + V_S_OFF;
    float* c_s  = sm + C_S_OFF;
    float* p_s  = sm + P_S_OFF;

    const int t    = threadIdx.x;
    const int bid  = blockIdx.x;
    const int b    = bid / NTILE;
    const int tile = bid - b * NTILE;
    const int x0   = tile * XT;

    const float* ub = u + (size_t)b * B_N * C_N * P_N * F2_N;

    // thread roles
    const int Bp = t >> 7;           // 0..1  (B' within chunk, dot phase)
    const int Cc = (t >> 3) & 15;    // C
    const int xx = t & 7;            // x within tile
    const int ph = t >> 7;           // p-half owner for s accumulation

    float sreg[8];

    for (int pass = 0; pass < 3; pass++) {
#pragma unroll
        for (int i = 0; i < 8; i++) sreg[i] = 0.f;

        prefetch_chunk(ub, u_s, 0, 0, x0, t);

        for (int ch = 0; ch < NCHUNK; ch++) {
            const int cur = ch & 1;
            if (ch + 1 < NCHUNK) {
                prefetch_chunk(ub, u_s, ch + 1, cur ^ 1, x0, t);
                asm volatile("cp.async.wait_group 1;\n");
            } else {
                asm volatile("cp.async.wait_group 0;\n");
            }
            __syncthreads();

            const float* ubuf = u_s + cur * (BCH * C_N * PLANE);

            if (pass > 0) {
                // --- dot over p: agreement with previous v ---
                const float* up = ubuf + (Bp * C_N + Cc) * PLANE + xx;
                const float* vp = v_s + Cc * PLANE + xx;
                float dot = 0.f;
#pragma unroll
                for (int p = 0; p < 16; p++)
                    dot = fmaf(up[p * XT], vp[p * XT], dot);
                const int ridx = ((ch * BCH + Bp) * C_N + Cc) * XT + xx;
                float rv = (pass == 1) ? dot : (r_s[ridx] + dot);
                r_s[ridx] = rv;
                __syncthreads();

                // --- softmax over C for this chunk's (B', x) pairs ---
                if (t < BCH * XT) {
                    const int Bl = t >> 3, xl = t & 7;
                    const float* rr = r_s + ((ch * BCH + Bl) * C_N) * XT + xl;
                    float m = -1e30f;
#pragma unroll
                    for (int cq = 0; cq < 16; cq++) m = fmaxf(m, rr[cq * XT]);
                    float e[16];
                    float ssum = 0.f;
#pragma unroll
                    for (int cq = 0; cq < 16; cq++) {
                        e[cq] = __expf(rr[cq * XT] - m);
                        ssum += e[cq];
                    }
                    const float inv = 1.f / ssum;
#pragma unroll
                    for (int cq = 0; cq < 16; cq++)
                        c_s[(Bl * C_N + cq) * XT + xl] = e[cq] * inv;
                }
                __syncthreads();
            }

            // --- accumulate s[C,p,x] += c * u ---
#pragma unroll
            for (int Bl = 0; Bl < BCH; Bl++) {
                const float cc = (pass == 0) ? 0.0625f
                                             : c_s[(Bl * C_N + Cc) * XT + xx];
                const float* uu = ubuf + (Bl * C_N + Cc) * PLANE + (ph * 8) * XT + xx;
#pragma unroll
                for (int i = 0; i < 8; i++)
                    sreg[i] = fmaf(cc, uu[i * XT], sreg[i]);
            }
        }

        // --- squash ---
        float partial = 0.f;
#pragma unroll
        for (int i = 0; i < 8; i++) partial += sreg[i] * sreg[i];
        p_s[(ph * C_N + Cc) * XT + xx] = partial;
        __syncthreads();
        const float sn = p_s[(0 * C_N + Cc) * XT + xx]
                       + p_s[(1 * C_N + Cc) * XT + xx];
        const float scale = sqrtf(sn) / (1.f + sn);

#pragma unroll
        for (int i = 0; i < 8; i++)
            v_s[Cc * PLANE + (ph * 8 + i) * XT + xx] = sreg[i] * scale;

        if (pass == 2 && ph == 0) {
            // a_out = |v| = sn/(1+sn)
            out[(size_t)V_ELEMS + ((size_t)b * C_N + Cc) * F2_N + x0 + xx] =
                sn / (1.f + sn);
        }
        __syncthreads();
    }

    // coalesced v write: 256 rows of (C,p), 8 floats each
    {
        const int Cr = t >> 4, pr = t & 15;
        const float4* src = (const float4*)(v_s + Cr * PLANE + pr * XT);
        float4* dst = (float4*)(out + (((size_t)b * C_N + Cr) * P_N + pr) * F2_N + x0);
        dst[0] = src[0];
        dst[1] = src[1];
    }
}

extern "C" void kernel_launch(void* const* d_in, const int* in_sizes, int n_in,
                              void* d_out, int out_size) {
    const float* u = (const float*)d_in[0];   // (8,144,16,16,12,12) f32
    float* out = (float*)d_out;               // v (8,16,16,144) then a_out (8,16,144)

    cudaFuncSetAttribute(caps_route_kernel,
                         cudaFuncAttributeMaxDynamicSharedMemorySize, SMEM_BYTES);
    caps_route_kernel<<<8 * NTILE, 256, SMEM_BYTES>>>(u, out);
}

// round 3
// speedup vs baseline: 1.2587x; 1.2587x over previous
#include <cuda_runtime.h>
#include <cuda_bf16.h>
#include <cstdint>

// CapsuleRouting: b=8, B=144, C=16, P2=16, f*f=144, ITERS=3
//  - input `a` cancels in softmax -> ignored
//  - 3 streaming passes over u; r-update + softmax + weighted-sum fused
//  - softmax over C done with warp shuffles (C lives in 16-lane groups)
//  - one __syncthreads per chunk; 5-stage cp.async pipeline (4 chunks in flight)

#define B_N    144
#define C_N    16
#define P_N    16
#define F2_N   144
#define XT     8             // x positions per block
#define NTILE  18            // 144 / XT
#define BCH    2             // B per chunk
#define NCHUNK 72            // 144 / BCH
#define PLANE  132           // P_N*XT + 4 pad
#define NSTG   5             // pipeline stages (NSTG-1 chunks in flight)

#define STG_FLOATS (BCH * C_N * PLANE)            // 4224
#define U_S_OFF    0
#define U_S_SIZE   (NSTG * STG_FLOATS)            // 21120
#define R_S_OFF    (U_S_OFF + U_S_SIZE)
#define R_S_SIZE   (B_N * C_N * XT)               // 18432
#define V_S_OFF    (R_S_OFF + R_S_SIZE)
#define V_S_SIZE   (C_N * PLANE)                  // 2112
#define SMEM_FLOATS (V_S_OFF + V_S_SIZE)          // 41664
#define SMEM_BYTES  (SMEM_FLOATS * 4)             // 166656

#define V_ELEMS (8 * C_N * P_N * F2_N)            // 294912

__device__ __forceinline__ void cp_async16(float* smem_dst, const float* gmem_src) {
    unsigned s = (unsigned)__cvta_generic_to_shared(smem_dst);
    asm volatile("cp.async.cg.shared.global [%0], [%1], 16;\n" :: "r"(s), "l"(gmem_src));
}

// prefetch one B-chunk (4096 floats) into smem stage
__device__ __forceinline__ void prefetch_chunk(const float* __restrict__ ub,
                                               float* __restrict__ u_s,
                                               int ch, int stg, int x0, int t) {
    float* dst = u_s + stg * STG_FLOATS;
    int B0 = ch * BCH;
#pragma unroll
    for (int k = 0; k < 4; k++) {
        int q    = t + k * 256;
        int row  = q >> 1;
        int half = q & 1;
        int Bl = row >> 8;
        int Cl = (row >> 4) & 15;
        int pl = row & 15;
        const float* g = ub + ((size_t)((B0 + Bl) * C_N + Cl) * P_N + pl) * F2_N
                            + x0 + half * 4;
        float* s = dst + (Bl * C_N + Cl) * PLANE + pl * XT + half * 4;
        cp_async16(s, g);
    }
    asm volatile("cp.async.commit_group;\n");
}

__global__ void __launch_bounds__(256, 1)
caps_route_kernel(const float* __restrict__ u, float* __restrict__ out) {
    extern __shared__ float sm[];
    float* u_s  = sm + U_S_OFF;
    float* r_s  = sm + R_S_OFF;
    float* v_s  = sm + V_S_OFF;
    float* tmp  = sm + U_S_OFF;          // aliases stage 0 (safe: see pass tail)

    const int t    = threadIdx.x;
    const int bid  = blockIdx.x;
    const int b    = bid / NTILE;
    const int tile = bid - b * NTILE;
    const int x0   = tile * XT;

    const float* ub = u + (size_t)b * B_N * C_N * P_N * F2_N;

    // compute mapping: t = Bp*128 + z*16 + Cc  (16-lane C groups for shuffles)
    const int Bp = t >> 7;
    const int z  = (t >> 4) & 7;
    const int Cc = t & 15;
    const int ubase_off = (Bp * C_N + Cc) * PLANE + z;

    float sreg[16], vreg[16];

    for (int pass = 0; pass < 3; pass++) {
#pragma unroll
        for (int i = 0; i < 16; i++) sreg[i] = 0.f;

        if (pass > 0) {
            // v from previous pass -> registers (reused for 72 chunks)
#pragma unroll
            for (int p = 0; p < 16; p++) vreg[p] = v_s[Cc * PLANE + p * XT + z];
        }

        // prologue: fill NSTG-1 stages
#pragma unroll
        for (int k = 0; k < NSTG - 1; k++) prefetch_chunk(ub, u_s, k, k, x0, t);

        int stg_next = NSTG - 1;   // stage for chunk ch+NSTG-1
        int stg_cur  = 0;

        for (int ch = 0; ch < NCHUNK; ch++) {
            // wait for chunk ch (tail-guarded)
            if      (ch + 3 < NCHUNK) asm volatile("cp.async.wait_group 3;\n");
            else if (ch + 2 < NCHUNK) asm volatile("cp.async.wait_group 2;\n");
            else if (ch + 1 < NCHUNK) asm volatile("cp.async.wait_group 1;\n");
            else                      asm volatile("cp.async.wait_group 0;\n");
            __syncthreads();   // data visible to all + stage (ch-1)%NSTG free

            if (ch + NSTG - 1 < NCHUNK) {
                prefetch_chunk(ub, u_s, ch + NSTG - 1, stg_next, x0, t);
                if (++stg_next == NSTG) stg_next = 0;
            }

            const float* ubase = u_s + stg_cur * STG_FLOATS + ubase_off;
            if (++stg_cur == NSTG) stg_cur = 0;

            float ureg[16];
#pragma unroll
            for (int p = 0; p < 16; p++) ureg[p] = ubase[p * XT];

            if (pass == 0) {
#pragma unroll
                for (int p = 0; p < 16; p++) sreg[p] += ureg[p];
            } else {
                // agreement dot over p
                float dot = 0.f;
#pragma unroll
                for (int p = 0; p < 16; p++) dot = fmaf(ureg[p], vreg[p], dot);

                const int ridx = ((ch * BCH + Bp) * C_N + Cc) * XT + z;
                float rv = (pass == 1) ? dot : (r_s[ridx] + dot);
                r_s[ridx] = rv;

                // softmax over C within 16-lane shuffle group
                float m = rv;
#pragma unroll
                for (int msk = 1; msk < 16; msk <<= 1)
                    m = fmaxf(m, __shfl_xor_sync(0xffffffffu, m, msk));
                float e = __expf(rv - m);
                float ssum = e;
#pragma unroll
                for (int msk = 1; msk < 16; msk <<= 1)
                    ssum += __shfl_xor_sync(0xffffffffu, ssum, msk);
                const float cc = __fdividef(e, ssum);

#pragma unroll
                for (int p = 0; p < 16; p++) sreg[p] = fmaf(cc, ureg[p], sreg[p]);
            }
        }

        // ---- squash: combine Bp halves via tmp (aliases stage 0, all async drained)
        const float w = (pass == 0) ? 0.0625f : 1.0f;
#pragma unroll
        for (int p = 0; p < 16; p++)
            tmp[(Bp * C_N + Cc) * PLANE + p * XT + z] = sreg[p] * w;
        __syncthreads();

        float sp[16];
        float sn = 0.f;
#pragma unroll
        for (int p = 0; p < 16; p++) {
            sp[p] = tmp[(0 * C_N + Cc) * PLANE + p * XT + z]
                  + tmp[(1 * C_N + Cc) * PLANE + p * XT + z];
            sn = fmaf(sp[p], sp[p], sn);
        }
        const float scale = sqrtf(sn) / (1.f + sn);

        __syncthreads();   // tmp reads done before stage 0 reused next pass

        if (Bp == 0) {
#pragma unroll
            for (int p = 0; p < 16; p++)
                v_s[Cc * PLANE + p * XT + z] = sp[p] * scale;
            if (pass == 2)
                out[(size_t)V_ELEMS + ((size_t)b * C_N + Cc) * F2_N + x0 + z] =
                    sn / (1.f + sn);
        }
        __syncthreads();
    }

    // coalesced v write: 256 rows of (C,p), 8 floats each
    {
        const int Cr = t >> 4, pr = t & 15;
        const float4* src = (const float4*)(v_s + Cr * PLANE + pr * XT);
        float4* dst = (float4*)(out + (((size_t)b * C_N + Cr) * P_N + pr) * F2_N + x0);
        dst[0] = src[0];
        dst[1] = src[1];
    }
}

extern "C" void kernel_launch(void* const* d_in, const int* in_sizes, int n_in,
                              void* d_out, int out_size) {
    const float* u = (const float*)d_in[0];   // (8,144,16,16,12,12) f32
    float* out = (float*)d_out;               // v (8,16,16,144) then a_out (8,16,144)

    cudaFuncSetAttribute(caps_route_kernel,
                         cudaFuncAttributeMaxDynamicSharedMemorySize, SMEM_BYTES);
    caps_route_kernel<<<8 * NTILE, 256, SMEM_BYTES>>>(u, out);
}

// round 4
// speedup vs baseline: 1.4873x; 1.1816x over previous
#include <cuda_runtime.h>
#include <cuda_bf16.h>
#include <cstdint>

// CapsuleRouting: b=8, B=144, C=16, P2=16, f*f=144, ITERS=3
//  - input `a` cancels in softmax -> ignored
//  - 3 streaming passes over u; r-update + softmax + weighted-sum fused
//  - softmax over C via 16-lane shuffles, no max-subtraction (|r| small)
//  - BCH=4 (2 independent chains/thread, ILP), NSTG=4 (3 chunks in flight),
//    one __syncthreads per chunk

#define B_N    144
#define C_N    16
#define P_N    16
#define F2_N   144
#define XT     8             // x positions per block
#define NTILE  18            // 144 / XT
#define BCH    4             // B per chunk
#define NCHUNK 36            // 144 / BCH
#define PLANE  132           // P_N*XT + 4 pad
#define NSTG   4

#define STG_FLOATS (BCH * C_N * PLANE)            // 8448
#define U_S_OFF    0
#define U_S_SIZE   (NSTG * STG_FLOATS)            // 33792
#define R_S_OFF    (U_S_OFF + U_S_SIZE)
#define R_S_SIZE   (B_N * C_N * XT)               // 18432
#define V_S_OFF    (R_S_OFF + R_S_SIZE)
#define V_S_SIZE   (C_N * PLANE)                  // 2112
#define SMEM_FLOATS (V_S_OFF + V_S_SIZE)          // 54336
#define SMEM_BYTES  (SMEM_FLOATS * 4)             // 217344

#define V_ELEMS (8 * C_N * P_N * F2_N)            // 294912

__device__ __forceinline__ void cp_async16(float* smem_dst, const float* gmem_src) {
    unsigned s = (unsigned)__cvta_generic_to_shared(smem_dst);
    asm volatile("cp.async.cg.shared.global [%0], [%1], 16;\n" :: "r"(s), "l"(gmem_src));
}

// prefetch one B-chunk (BCH*C_N*P_N*XT = 8192 floats) into smem stage
__device__ __forceinline__ void prefetch_chunk(const float* __restrict__ ub,
                                               float* __restrict__ u_s,
                                               int ch, int stg, int x0, int t) {
    float* dst = u_s + stg * STG_FLOATS;
    int B0 = ch * BCH;
#pragma unroll
    for (int k = 0; k < 8; k++) {
        int q    = t + k * 256;        // 0..2047 float4 slots
        int row  = q >> 1;             // (Bl, Cl, pl)
        int half = q & 1;
        int Bl = row >> 8;             // 0..3
        int Cl = (row >> 4) & 15;
        int pl = row & 15;
        const float* g = ub + ((size_t)((B0 + Bl) * C_N + Cl) * P_N + pl) * F2_N
                            + x0 + half * 4;
        float* s = dst + (Bl * C_N + Cl) * PLANE + pl * XT + half * 4;
        cp_async16(s, g);
    }
    asm volatile("cp.async.commit_group;\n");
}

__global__ void __launch_bounds__(256, 1)
caps_route_kernel(const float* __restrict__ u, float* __restrict__ out) {
    extern __shared__ float sm[];
    float* u_s  = sm + U_S_OFF;
    float* r_s  = sm + R_S_OFF;
    float* v_s  = sm + V_S_OFF;
    float* tmp  = sm + U_S_OFF;          // aliases stage 0 (safe at pass tail)

    const int t    = threadIdx.x;
    const int bid  = blockIdx.x;
    const int b    = bid / NTILE;
    const int tile = bid - b * NTILE;
    const int x0   = tile * XT;

    const float* ub = u + (size_t)b * B_N * C_N * P_N * F2_N;

    // mapping: t = Bp*128 + z*16 + Cc  (16-lane C groups for shuffles)
    const int Bp = t >> 7;               // thread handles Bl = 2*Bp + {0,1}
    const int z  = (t >> 4) & 7;
    const int Cc = t & 15;

    float sreg[16], vreg[16];

    for (int pass = 0; pass < 3; pass++) {
#pragma unroll
        for (int i = 0; i < 16; i++) sreg[i] = 0.f;

        if (pass > 0) {
#pragma unroll
            for (int p = 0; p < 16; p++) vreg[p] = v_s[Cc * PLANE + p * XT + z];
        }

        // prologue: fill 3 stages
#pragma unroll
        for (int k = 0; k < NSTG - 1; k++) prefetch_chunk(ub, u_s, k, k, x0, t);

        for (int ch = 0; ch < NCHUNK; ch++) {
            if      (ch <= NCHUNK - 3) asm volatile("cp.async.wait_group 2;\n");
            else if (ch == NCHUNK - 2) asm volatile("cp.async.wait_group 1;\n");
            else                       asm volatile("cp.async.wait_group 0;\n");
            __syncthreads();   // chunk ch visible; compute(ch-1) done by all

            if (ch + NSTG - 1 < NCHUNK)
                prefetch_chunk(ub, u_s, ch + NSTG - 1, (ch + NSTG - 1) & 3, x0, t);

            const float* ubuf = u_s + (ch & 3) * STG_FLOATS;

#pragma unroll
            for (int j = 0; j < 2; j++) {
                const int Bl = Bp * 2 + j;
                const float* ub2 = ubuf + (Bl * C_N + Cc) * PLANE + z;
                float ureg[16];
#pragma unroll
                for (int p = 0; p < 16; p++) ureg[p] = ub2[p * XT];

                if (pass == 0) {
#pragma unroll
                    for (int p = 0; p < 16; p++) sreg[p] += ureg[p];
                } else {
                    float dot = 0.f;
#pragma unroll
                    for (int p = 0; p < 16; p++) dot = fmaf(ureg[p], vreg[p], dot);

                    const int ridx = ((ch * BCH + Bl) * C_N + Cc) * XT + z;
                    float rv = (pass == 1) ? dot : (r_s[ridx] + dot);
                    r_s[ridx] = rv;

                    // softmax over C (no max-subtraction; |rv| <~ 16)
                    float e = __expf(rv);
                    float ssum = e;
#pragma unroll
                    for (int msk = 1; msk < 16; msk <<= 1)
                        ssum += __shfl_xor_sync(0xffffffffu, ssum, msk);
                    const float cc = __fdividef(e, ssum);

#pragma unroll
                    for (int p = 0; p < 16; p++) sreg[p] = fmaf(cc, ureg[p], sreg[p]);
                }
            }
        }

        // ---- squash: combine Bp halves via tmp (stage 0; all async drained)
        const float w = (pass == 0) ? 0.0625f : 1.0f;
#pragma unroll
        for (int p = 0; p < 16; p++)
            tmp[(Bp * C_N + Cc) * PLANE + p * XT + z] = sreg[p] * w;
        __syncthreads();

        float sp[16];
        float sn = 0.f;
#pragma unroll
        for (int p = 0; p < 16; p++) {
            sp[p] = tmp[(0 * C_N + Cc) * PLANE + p * XT + z]
                  + tmp[(1 * C_N + Cc) * PLANE + p * XT + z];
            sn = fmaf(sp[p], sp[p], sn);
        }
        const float scale = sqrtf(sn) / (1.f + sn);

        __syncthreads();   // tmp reads done before stage 0 reused next pass

        if (Bp == 0) {
#pragma unroll
            for (int p = 0; p < 16; p++)
                v_s[Cc * PLANE + p * XT + z] = sp[p] * scale;
            if (pass == 2)
                out[(size_t)V_ELEMS + ((size_t)b * C_N + Cc) * F2_N + x0 + z] =
                    sn / (1.f + sn);
        }
        __syncthreads();
    }

    // coalesced v write: 256 rows of (C,p), 8 floats each
    {
        const int Cr = t >> 4, pr = t & 15;
        const float4* src = (const float4*)(v_s + Cr * PLANE + pr * XT);
        float4* dst = (float4*)(out + (((size_t)b * C_N + Cr) * P_N + pr) * F2_N + x0);
        dst[0] = src[0];
        dst[1] = src[1];
    }
}

extern "C" void kernel_launch(void* const* d_in, const int* in_sizes, int n_in,
                              void* d_out, int out_size) {
    const float* u = (const float*)d_in[0];   // (8,144,16,16,12,12) f32
    float* out = (float*)d_out;               // v (8,16,16,144) then a_out (8,16,144)

    cudaFuncSetAttribute(caps_route_kernel,
                         cudaFuncAttributeMaxDynamicSharedMemorySize, SMEM_BYTES);
    caps_route_kernel<<<8 * NTILE, 256, SMEM_BYTES>>>(u, out);
}